// round 8
// baseline (speedup 1.0000x reference)
#include <cuda_runtime.h>

// Depthwise 3x3 lateral conv (center tap excluded) + residual, NHWC f32.
// x: [32,56,56,256], kernel: [3,3,256], out: [32,56,56,256]
//
// R8: taller register tile HR=4 x WR=4 (float2 channels) cuts read
// amplification from 3.0 to 2.25 loads/output: 6x6 input positions feed
// 4x4 outputs per thread. Rows load/consume in sequence (6 loads per row)
// so only ~3 input rows are live at once (~100 regs, launch_bounds(128,4)).
// Interior blocks (~86%) take the branch-free immediate-offset path.
// Taps in registers; residual folded as center-pixel add.

#define H 56
#define W 56
#define C2 128        // channels as float2
#define HR 4
#define WR 4

__device__ __forceinline__ void f2fma(float2& a, float2 v, float2 k) {
    a.x = fmaf(v.x, k.x, a.x);
    a.y = fmaf(v.y, k.y, a.y);
}

__global__ __launch_bounds__(128, 4) void contour_kernel(
    const float* __restrict__ x,
    const float* __restrict__ kern,
    float* __restrict__ out)
{
    const int c2 = threadIdx.x;              // 0..127 (2 channels)
    const int wb = blockIdx.x * WR;          // 0,4,...,52
    const int hb = blockIdx.y * HR;          // 0,4,...,52
    const int b  = blockIdx.z;

    const float2* __restrict__ xin = reinterpret_cast<const float2*>(x);
    const float2* __restrict__ k2  = reinterpret_cast<const float2*>(kern);
    float2* __restrict__ o = reinterpret_cast<float2*>(out);

    // 8 lateral taps -> registers (center excluded; residual = center add)
    float2 kreg[8];
    #pragma unroll
    for (int t = 0; t < 8; t++) {
        const int tap = t + (t >= 4 ? 1 : 0);
        kreg[t] = k2[tap * C2 + c2];
    }

    const int img = b * (H * W * C2);

    float2 acc[HR][WR];
    #pragma unroll
    for (int r = 0; r < HR; r++)
        #pragma unroll
        for (int j = 0; j < WR; j++)
            acc[r][j] = make_float2(0.f, 0.f);

    const bool interior = (hb >= 1) & (hb + HR + 1 <= H) & (wb >= 1) & (wb + WR + 1 <= W);

    if (interior) {
        const float2* __restrict__ p =
            xin + img + ((hb - 1) * W + (wb - 1)) * C2 + c2;

        #pragma unroll
        for (int ih = 0; ih < HR + 2; ih++) {
            float2 v[WR + 2];
            #pragma unroll
            for (int j = 0; j < WR + 2; j++)
                v[j] = p[(ih * W + j) * C2];

            #pragma unroll
            for (int r = 0; r < HR; r++) {
                const int kh = ih - r;
                if (kh < 0 || kh > 2) continue;
                #pragma unroll
                for (int dw = 0; dw < 3; dw++) {
                    const bool is_center = (kh == 1 && dw == 1);
                    const int lin = kh * 3 + dw;
                    const int t = lin - (lin > 4 ? 1 : 0);
                    #pragma unroll
                    for (int j = 0; j < WR; j++) {
                        if (is_center) {
                            acc[r][j].x += v[j + 1].x;   // residual
                            acc[r][j].y += v[j + 1].y;
                        } else {
                            f2fma(acc[r][j], v[j + dw], kreg[t]);
                        }
                    }
                }
            }
        }
    } else {
        #pragma unroll
        for (int ih = 0; ih < HR + 2; ih++) {
            const int row = hb - 1 + ih;
            if (row < 0 || row >= H) continue;
            const int rb = img + row * (W * C2) + c2;

            float2 v[WR + 2];
            #pragma unroll
            for (int j = 0; j < WR + 2; j++) {
                const int col = wb - 1 + j;
                v[j] = ((unsigned)col < (unsigned)W) ? xin[rb + col * C2]
                                                     : make_float2(0.f, 0.f);
            }

            #pragma unroll
            for (int r = 0; r < HR; r++) {
                const int kh = ih - r;
                if (kh < 0 || kh > 2) continue;
                #pragma unroll
                for (int dw = 0; dw < 3; dw++) {
                    const bool is_center = (kh == 1 && dw == 1);
                    const int lin = kh * 3 + dw;
                    const int t = lin - (lin > 4 ? 1 : 0);
                    #pragma unroll
                    for (int j = 0; j < WR; j++) {
                        if (is_center) {
                            acc[r][j].x += v[j + 1].x;
                            acc[r][j].y += v[j + 1].y;
                        } else {
                            f2fma(acc[r][j], v[j + dw], kreg[t]);
                        }
                    }
                }
            }
        }
    }

    #pragma unroll
    for (int r = 0; r < HR; r++) {
        const int rb = img + (hb + r) * (W * C2) + c2;
        #pragma unroll
        for (int j = 0; j < WR; j++)
            o[rb + (wb + j) * C2] = acc[r][j];
    }
}

extern "C" void kernel_launch(void* const* d_in, const int* in_sizes, int n_in,
                              void* d_out, int out_size)
{
    const float* x    = (const float*)d_in[0];   // [32,56,56,256]
    const float* kern = (const float*)d_in[1];   // [3,3,256]
    float* outp       = (float*)d_out;

    dim3 block(C2, 1, 1);            // 128 threads
    dim3 grid(W / WR, H / HR, 32);   // 14 x 14 x 32 = 6272 blocks
    contour_kernel<<<grid, block>>>(x, kern, outp);
}